// round 15
// baseline (speedup 1.0000x reference)
#include <cuda_runtime.h>
#include <cuda_bf16.h>
#include <math.h>
#include <stdint.h>

#define H        4096
#define E        64
#define TM       128              // tokens per block
#define KC       64               // k per chunk
#define NC       (H / KC)         // 64
#define NTHREADS 512

// dynamic smem (bytes): X limbs [buf][limb] 128x128B, then W limbs [buf][limb] 64x128B
#define XB(buf, limb) (((buf) << 15) + ((limb) << 14))
#define WOFF 65536
#define WB(buf, limb) (WOFF + ((buf) << 14) + ((limb) << 13))
#define SMEM_BYTES 98304

// W limbs (scale folded), [limb][expert*512 + k/8], 16B-aligned for cp.async
__device__ uint4 g_wl[2][E * (H / 8)];

static __device__ __forceinline__ void split2(float x, float y, uint32_t& hi, uint32_t& lo) {
    asm("cvt.rn.bf16x2.f32 %0, %1, %2;" : "=r"(hi) : "f"(y), "f"(x));   // low16 = bf16(x)
    const float hx = __uint_as_float(hi << 16);
    const float hy = __uint_as_float(hi & 0xFFFF0000u);
    const float rx = x - hx, ry = y - hy;
    asm("cvt.rn.bf16x2.f32 %0, %1, %2;" : "=r"(lo) : "f"(ry), "f"(rx));
}

__global__ void wprep_kernel(const float* __restrict__ wg, const float* __restrict__ sg)
{
    const int e = blockIdx.x;
    const int t = threadIdx.x;
    #pragma unroll
    for (int i = 0; i < 2; i++) {
        const int u = t + 256 * i;          // uint4 index within row (0..511) = 8 floats
        const float4 wA = ((const float4*)(wg + (size_t)e * H))[u * 2];
        const float4 wB = ((const float4*)(wg + (size_t)e * H))[u * 2 + 1];
        const float4 sA = ((const float4*)sg)[u * 2];
        const float4 sB = ((const float4*)sg)[u * 2 + 1];
        float4 a = wA, b = wB;
        a.x *= sA.x; a.y *= sA.y; a.z *= sA.z; a.w *= sA.w;
        b.x *= sB.x; b.y *= sB.y; b.z *= sB.z; b.w *= sB.w;
        uint32_t h0, l0, h1, l1, h2, l2, h3, l3;
        split2(a.x, a.y, h0, l0);  split2(a.z, a.w, h1, l1);
        split2(b.x, b.y, h2, l2);  split2(b.z, b.w, h3, l3);
        g_wl[0][e * 512 + u] = make_uint4(h0, h1, h2, h3);
        g_wl[1][e * 512 + u] = make_uint4(l0, l1, l2, l3);
    }
}

#define LDSM4(r0, r1, r2, r3, addr) \
    asm volatile("ldmatrix.sync.aligned.m8n8.x4.shared.b16 {%0,%1,%2,%3}, [%4];" \
                 : "=r"(r0), "=r"(r1), "=r"(r2), "=r"(r3) : "r"(addr))

#define MMA(acc, a, b0, b1) \
    asm volatile("mma.sync.aligned.m16n8k16.row.col.f32.bf16.bf16.f32 " \
                 "{%0,%1,%2,%3},{%4,%5,%6,%7},{%8,%9},{%0,%1,%2,%3};" \
                 : "+f"((acc)[0]), "+f"((acc)[1]), "+f"((acc)[2]), "+f"((acc)[3]) \
                 : "r"((a)[0]), "r"((a)[1]), "r"((a)[2]), "r"((a)[3]), "r"(b0), "r"(b1))

#define STS128(addr, v0, v1, v2, v3) \
    asm volatile("st.shared.v4.b32 [%0], {%1,%2,%3,%4};" \
                 :: "r"(addr), "r"(v0), "r"(v1), "r"(v2), "r"(v3))

#define CPASYNC16(dst, src) \
    asm volatile("cp.async.ca.shared.global [%0], [%1], 16;" :: "r"(dst), "l"(src))

// out layout (fp32): probs[ntok][64] | top_k_weights[ntok][2] | top_k_index[ntok][2]

__global__ __launch_bounds__(NTHREADS, 1)
void router_kernel(const float* __restrict__ xg, const float* __restrict__ pes,
                   float* __restrict__ out, int ntok)
{
    extern __shared__ char smem[];
    __shared__ float ssq[TM];
    __shared__ float topw[TM * 2];
    __shared__ float topi[TM * 2];

    uint32_t sb;
    asm("{ .reg .u64 t; cvta.to.shared.u64 t, %1; cvt.u32.u64 %0, t; }" : "=r"(sb) : "l"(smem));

    const int tid  = threadIdx.x;
    const int lane = tid & 31;
    const int wid  = tid >> 5;
    const int tok0 = blockIdx.x * TM;
    if (tid < TM) ssq[tid] = 0.f;

    // ---- duty groups: A = kg 0 (wid 0..7), B = kg 1 (wid 8..15)
    const int kg   = wid >> 3;
    const int gtid = ((wid & 7) << 5) | lane;      // 0..255 within group

    // ---- staging assignment (fixed per thread): row sr, 32-float half
    const int sr    = gtid >> 1;
    const int shalf = gtid & 1;
    const float* xsrow = xg + (size_t)(tok0 + sr) * H + shalf * 32;
    const uint32_t srx = (uint32_t)(sr & 7);
    // W duty: limb swl, expert row swr, 4 x 16B
    const int swl  = gtid >> 7;
    const int swr  = (gtid >> 1) & 63;
    const int swc0 = (gtid & 1) * 4;
    const char* wsrc_base = (const char*)&g_wl[swl][swr * 512];
    const uint32_t wxor = (uint32_t)(swr & 7);
    float ssql = 0.f;

    // ---- MMA assignment (within group): 4 m-tiles(m32) x 2 n-tiles(n32) — R11 geometry
    const int widg = wid & 7;
    const int m0   = ((widg >> 1) & 3) << 5;
    const int n0   = (widg & 1) << 5;
    const int arow0 = m0 + (lane & 15);
    const int arow1 = arow0 + 16;
    const int apar  = lane >> 4;
    const int axor  = arow0 & 7;
    const int brow_in = (lane & 7) + ((lane >> 4) << 3);
    const int bpar    = (lane >> 3) & 1;

    float acc[2][4][4];
    #pragma unroll
    for (int mt = 0; mt < 2; mt++)
        #pragma unroll
        for (int nt = 0; nt < 4; nt++)
            #pragma unroll
            for (int j = 0; j < 4; j++) acc[mt][nt][j] = 0.f;

// stage chunk cc into buffer b: 32 X floats + 64 W bytes per thread (group-wide: full chunk)
#define STAGE(cc, b) do {                                                            \
    const size_t ko = (size_t)(cc) * KC;                                             \
    float4 xv0 = *(const float4*)(xsrow + ko);                                       \
    float4 xv1 = *(const float4*)(xsrow + ko + 4);                                   \
    float4 xv2 = *(const float4*)(xsrow + ko + 8);                                   \
    float4 xv3 = *(const float4*)(xsrow + ko + 12);                                  \
    float4 xv4 = *(const float4*)(xsrow + ko + 16);                                  \
    float4 xv5 = *(const float4*)(xsrow + ko + 20);                                  \
    float4 xv6 = *(const float4*)(xsrow + ko + 24);                                  \
    float4 xv7 = *(const float4*)(xsrow + ko + 28);                                  \
    {                                                                                \
        const uint32_t wdst = sb + WB(b, swl) + (uint32_t)swr * 128;                 \
        const char* ws = wsrc_base + (size_t)(cc) * 128;                             \
        _Pragma("unroll")                                                            \
        for (int j = 0; j < 4; j++) {                                                \
            const uint32_t ccu = (uint32_t)(swc0 + j);                               \
            CPASYNC16(wdst + ((ccu ^ wxor) << 4), ws + ccu * 16);                    \
        }                                                                            \
        asm volatile("cp.async.commit_group;" ::: "memory");                         \
    }                                                                                \
    {                                                                                \
        const uint32_t rb = sb + XB(b, 0) + (uint32_t)sr * 128;                      \
        _Pragma("unroll")                                                            \
        for (int j = 0; j < 4; j++) {                                                \
            float4 a, bb;                                                            \
            switch (j) {                                                             \
                case 0: a = xv0; bb = xv1; break;                                    \
                case 1: a = xv2; bb = xv3; break;                                    \
                case 2: a = xv4; bb = xv5; break;                                    \
                default: a = xv6; bb = xv7; break;                                   \
            }                                                                        \
            ssql += a.x*a.x + a.y*a.y + a.z*a.z + a.w*a.w                            \
                  + bb.x*bb.x + bb.y*bb.y + bb.z*bb.z + bb.w*bb.w;                   \
            uint32_t h0,l0,h1,l1,h2,l2,h3,l3;                                        \
            split2(a.x,  a.y,  h0, l0);  split2(a.z,  a.w,  h1, l1);                 \
            split2(bb.x, bb.y, h2, l2);  split2(bb.z, bb.w, h3, l3);                 \
            const uint32_t d = rb + ((((uint32_t)(shalf * 4 + j)) ^ srx) << 4);      \
            STS128(d,         h0, h1, h2, h3);                                       \
            STS128(d + 16384, l0, l1, l2, l3);                                       \
        }                                                                            \
    }                                                                                \
    asm volatile("cp.async.wait_group 0;" ::: "memory");                             \
} while (0)

    // ---- prologue: group A stages chunk 0
    if (kg == 0) { STAGE(0, 0); }
    __syncthreads();

    for (int c = 0; c < NC; c++) {
        const int buf = c & 1;
        if (kg == buf) {
            // ---- MMA chunk c (R11 inner loop verbatim)
            #pragma unroll
            for (int ks = 0; ks < 4; ks++) {
                uint32_t A[2][2][4];               // [limb][mt]
                const uint32_t ao = (uint32_t)((((ks << 1) + apar) ^ axor) << 4);
                #pragma unroll
                for (int l = 0; l < 2; l++) {
                    const uint32_t xb = sb + XB(buf, l);
                    LDSM4(A[l][0][0], A[l][0][1], A[l][0][2], A[l][0][3],
                          xb + (uint32_t)arow0 * 128 + ao);
                    LDSM4(A[l][1][0], A[l][1][1], A[l][1][2], A[l][1][3],
                          xb + (uint32_t)arow1 * 128 + ao);
                }
                #pragma unroll
                for (int ng = 0; ng < 2; ng++) {   // n16 groups within n32
                    const int brow = n0 + ng * 16 + brow_in;
                    const uint32_t bo = (uint32_t)((((ks << 1) + bpar) ^ (brow & 7)) << 4)
                                      + (uint32_t)brow * 128;
                    uint32_t B0[4], B1[4];
                    LDSM4(B0[0], B0[1], B0[2], B0[3], sb + WB(buf, 0) + bo);
                    LDSM4(B1[0], B1[1], B1[2], B1[3], sb + WB(buf, 1) + bo);
                    #pragma unroll
                    for (int mt = 0; mt < 2; mt++) {
                        MMA(acc[mt][ng * 2],     A[0][mt], B0[0], B0[1]);   // hi*hi
                        MMA(acc[mt][ng * 2],     A[0][mt], B1[0], B1[1]);   // hi*lo
                        MMA(acc[mt][ng * 2],     A[1][mt], B0[0], B0[1]);   // lo*hi
                        MMA(acc[mt][ng * 2 + 1], A[0][mt], B0[2], B0[3]);
                        MMA(acc[mt][ng * 2 + 1], A[0][mt], B1[2], B1[3]);
                        MMA(acc[mt][ng * 2 + 1], A[1][mt], B0[2], B0[3]);
                    }
                }
            }
        } else if (c + 1 < NC) {
            STAGE(c + 1, (c + 1) & 1);
        }
        __syncthreads();
    }

    atomicAdd(&ssq[sr], ssql);
    __syncthreads();

    // ---- K-group reduction into padded score tile sc[128][68]
    float* sc = (float*)smem;
    {
        const int colb = n0 + (lane & 3) * 2;
        if (kg == 0) {
            #pragma unroll
            for (int mt = 0; mt < 2; mt++) {
                const int row0 = m0 + mt * 16 + (lane >> 2);
                #pragma unroll
                for (int nt = 0; nt < 4; nt++) {
                    const int col = colb + nt * 8;
                    sc[row0 * 68 + col]           = acc[mt][nt][0];
                    sc[row0 * 68 + col + 1]       = acc[mt][nt][1];
                    sc[(row0 + 8) * 68 + col]     = acc[mt][nt][2];
                    sc[(row0 + 8) * 68 + col + 1] = acc[mt][nt][3];
                }
            }
        }
        __syncthreads();
        if (kg == 1) {
            #pragma unroll
            for (int mt = 0; mt < 2; mt++) {
                const int row0 = m0 + mt * 16 + (lane >> 2);
                #pragma unroll
                for (int nt = 0; nt < 4; nt++) {
                    const int col = colb + nt * 8;
                    sc[row0 * 68 + col]           += acc[mt][nt][0];
                    sc[row0 * 68 + col + 1]       += acc[mt][nt][1];
                    sc[(row0 + 8) * 68 + col]     += acc[mt][nt][2];
                    sc[(row0 + 8) * 68 + col + 1] += acc[mt][nt][3];
                }
            }
        }
    }
    __syncthreads();

    // ---- per-token RMSNorm factor + softmax + top-2
    if (tid < TM) {
        const int t = tid;
        const float rr = 1.0f / (64.0f * sqrtf(ssq[t] * (1.0f / 4096.0f) + 1e-6f));
        float m = -1e30f;
        #pragma unroll 8
        for (int e = 0; e < E; e++) m = fmaxf(m, sc[t * 68 + e] * rr);
        float sum = 0.f, m1 = -1.f, m2 = -1.f;
        int i1 = 0, i2 = 0;
        for (int e = 0; e < E; e++) {
            const float ex = __expf(sc[t * 68 + e] * rr - m);
            sum += ex;
            sc[t * 68 + e] = ex;
            if (ex > m1)      { m2 = m1; i2 = i1; m1 = ex; i1 = e; }
            else if (ex > m2) { m2 = ex; i2 = e; }
        }
        const float inv = 1.0f / sum;
        #pragma unroll 8
        for (int e = 0; e < E; e++) sc[t * 68 + e] *= inv;
        const float dn = 1.0f / (m1 + m2);
        topw[t * 2 + 0] = m1 * dn * pes[i1];
        topw[t * 2 + 1] = m2 * dn * pes[i2];
        topi[t * 2 + 0] = (float)i1;
        topi[t * 2 + 1] = (float)i2;
    }
    __syncthreads();

    // ---- outputs (2048 float4 of probs)
    float4* pout = (float4*)(out + (size_t)tok0 * 64);
    #pragma unroll
    for (int q = 0; q < 4; q++) {
        const int idx = tid + NTHREADS * q;
        const int row = idx >> 4;
        const int c4  = idx & 15;
        pout[idx] = *(const float4*)&sc[row * 68 + c4 * 4];
    }
    float* wout = out + (size_t)ntok * 64;
    float* iout = wout + (size_t)ntok * 2;
    if (tid < TM * 2) {
        wout[tok0 * 2 + tid] = topw[tid];
        iout[tok0 * 2 + tid] = topi[tid];
    }
}

extern "C" void kernel_launch(void* const* d_in, const int* in_sizes, int n_in,
                              void* d_out, int out_size)
{
    (void)n_in; (void)out_size;
    const float* x   = (const float*)d_in[0];
    const float* w   = (const float*)d_in[1];
    const float* s   = (const float*)d_in[2];
    const float* pes = (const float*)d_in[3];
    const int ntok = in_sizes[0] / H;            // 16384
    wprep_kernel<<<E, 256>>>(w, s);
    cudaFuncSetAttribute(router_kernel, cudaFuncAttributeMaxDynamicSharedMemorySize, SMEM_BYTES);
    router_kernel<<<ntok / TM, NTHREADS, SMEM_BYTES>>>(x, pes, (float*)d_out, ntok);
}